// round 4
// baseline (speedup 1.0000x reference)
#include <cuda_runtime.h>
#include <cuda_bf16.h>

// SNN Leaky (snntorch, reset='subtract'), arithmetic FROZEN (bit-matches R1 pass):
//   reset = (mem > 1) ? 1 : 0
//   mem   = ((0.95*mem) + x) - reset   [strict __fmul_rn/__fadd_rn/__fsub_rn]
//   spk   = (mem > 1) ? 1 : 0
// Output flat [T, N], N = 3145728, T = 50. HBM-write-bound (629 MB stream).
//
// R4 change: single balanced wave. 1024 blocks x 256 threads, 3 float4 columns
// per thread (1024*256*3 == n4 exactly). 6.9 blocks/SM all resident at once ->
// no wave transitions, no ragged tail; DRAM stays saturated end-to-end.
// __launch_bounds__(256,7) keeps regs <= 36 so 7 blocks/SM fit the RF.

#define SNN_THREADS 256
#define BETA 0.95f
#define THR  1.0f

__device__ __forceinline__ void snn_step(float& m, float xv, float& s)
{
    const float r = (m > THR) ? THR : 0.0f;
    m = __fsub_rn(__fadd_rn(__fmul_rn(BETA, m), xv), r);
    s = (m > THR) ? 1.0f : 0.0f;
}

// Fixed-shape fast path: n4 == 3 * gridDim.x * blockDim.x, NSTEPS compile-time.
template <int NSTEPS>
__global__ __launch_bounds__(SNN_THREADS, 7)
void snn_kernel_v4(const float4* __restrict__ x, float4* __restrict__ out, int n4)
{
    const int nthreads = gridDim.x * SNN_THREADS;            // 262,144
    const int i0 = blockIdx.x * SNN_THREADS + threadIdx.x;   // column 0
    const int i1 = i0 + nthreads;                            // column 1
    const int i2 = i1 + nthreads;                            // column 2

    const float4 xa = x[i0];
    const float4 xb = x[i1];
    const float4 xc = x[i2];

    float a0 = 0.f, a1 = 0.f, a2 = 0.f, a3 = 0.f;
    float b0 = 0.f, b1 = 0.f, b2 = 0.f, b3 = 0.f;
    float c0 = 0.f, c1 = 0.f, c2 = 0.f, c3 = 0.f;

#pragma unroll
    for (int t = 0; t < NSTEPS; ++t) {
        float4 sa, sb, sc;
        snn_step(a0, xa.x, sa.x);
        snn_step(a1, xa.y, sa.y);
        snn_step(a2, xa.z, sa.z);
        snn_step(a3, xa.w, sa.w);
        snn_step(b0, xb.x, sb.x);
        snn_step(b1, xb.y, sb.y);
        snn_step(b2, xb.z, sb.z);
        snn_step(b3, xb.w, sb.w);
        snn_step(c0, xc.x, sc.x);
        snn_step(c1, xc.y, sc.y);
        snn_step(c2, xc.z, sc.z);
        snn_step(c3, xc.w, sc.w);

        float4* o = out + (size_t)t * n4;
        __stcs(o + i0, sa);
        __stcs(o + i1, sb);
        __stcs(o + i2, sc);
    }
}

// Generic runtime path (R1 structure): one float4 per thread.
__global__ __launch_bounds__(SNN_THREADS)
void snn_kernel_gen4(const float4* __restrict__ x, float4* __restrict__ out,
                     int n4, int nsteps)
{
    int i = blockIdx.x * SNN_THREADS + threadIdx.x;
    if (i >= n4) return;

    const float4 xv = x[i];
    float m0 = 0.f, m1 = 0.f, m2 = 0.f, m3 = 0.f;
    float4* o = out + i;

    for (int t = 0; t < nsteps; ++t) {
        float4 s;
        snn_step(m0, xv.x, s.x);
        snn_step(m1, xv.y, s.y);
        snn_step(m2, xv.z, s.z);
        snn_step(m3, xv.w, s.w);
        __stcs(o + (size_t)t * n4, s);
    }
}

// Scalar tail for n % 4 != 0 (not hit for this shape).
__global__ __launch_bounds__(SNN_THREADS)
void snn_kernel_tail(const float* __restrict__ x, float* __restrict__ out,
                     int start, int n, int nsteps)
{
    int i = start + blockIdx.x * SNN_THREADS + threadIdx.x;
    if (i >= n) return;

    const float xv = x[i];
    float m = 0.0f;
    for (int t = 0; t < nsteps; ++t) {
        float s;
        snn_step(m, xv, s);
        out[(size_t)t * n + i] = s;
    }
}

extern "C" void kernel_launch(void* const* d_in, const int* in_sizes, int n_in,
                              void* d_out, int out_size)
{
    const float* x = (const float*)d_in[0];
    float* out = (float*)d_out;

    const int n = in_sizes[0];          // 3,145,728
    const int nsteps = out_size / n;    // 50

    const int n4 = n / 4;               // 786,432
    const int COLS = 3;
    const int per_wave = 1024 * SNN_THREADS * COLS;   // 786,432

    if (nsteps == 50 && n4 == per_wave) {
        // single perfectly-balanced wave: 1024 blocks, 3 columns/thread
        snn_kernel_v4<50><<<1024, SNN_THREADS>>>(
            (const float4*)x, (float4*)out, n4);
    } else {
        const int tail = n - n4 * 4;
        if (n4 > 0) {
            const int grid = (n4 + SNN_THREADS - 1) / SNN_THREADS;
            snn_kernel_gen4<<<grid, SNN_THREADS>>>(
                (const float4*)x, (float4*)out, n4, nsteps);
        }
        if (tail > 0) {
            snn_kernel_tail<<<1, SNN_THREADS>>>(x, out, n4 * 4, n, nsteps);
        }
    }
}

// round 5
// speedup vs baseline: 1.7386x; 1.7386x over previous
#include <cuda_runtime.h>
#include <cuda_bf16.h>

// SNN Leaky (snntorch, reset='subtract'), arithmetic FROZEN (bit-matches R1 pass):
//   reset = (mem > 1) ? 1 : 0
//   mem   = ((0.95*mem) + x) - reset   [strict __fmul_rn/__fadd_rn/__fsub_rn]
//   spk   = (mem > 1) ? 1 : 0
// Output flat [T, N], N = 3145728, T = 50.
//
// ROOFLINE VERDICT (R1-R4 evidence): 642 MB of traffic in 94.4 us = 6.8 TB/s
// effective, ~85% of HBM spec — the write-stream ceiling. Probes that failed:
//   R2  2x STG.128/thread (store MLP)      -> neutral (97.0)
//   R3  STG.256/thread (request size)      -> neutral (98.8)
//   R4  3 spread columns (wave balance)    -> regression (163.9; page/row
//       locality loss + occupancy drop)
// Final form = R1: one float4 column per thread, one streaming STG.128 per
// step, contiguous per-warp 512B bursts, grid 3072 x 256, full unroll.

#define SNN_THREADS 256
#define BETA 0.95f
#define THR  1.0f

template <int NSTEPS>
__global__ __launch_bounds__(SNN_THREADS)
void snn_kernel_fixed(const float4* __restrict__ x, float4* __restrict__ out, int n4)
{
    int i = blockIdx.x * SNN_THREADS + threadIdx.x;
    if (i >= n4) return;

    const float4 xv = x[i];
    float m0 = 0.0f, m1 = 0.0f, m2 = 0.0f, m3 = 0.0f;
    float4* o = out + i;

#pragma unroll
    for (int t = 0; t < NSTEPS; ++t) {
        // reset from PREVIOUS mem
        const float r0 = (m0 > THR) ? THR : 0.0f;
        const float r1 = (m1 > THR) ? THR : 0.0f;
        const float r2 = (m2 > THR) ? THR : 0.0f;
        const float r3 = (m3 > THR) ? THR : 0.0f;
        // mem = ((beta*mem) + x) - reset, exact reference order
        m0 = __fsub_rn(__fadd_rn(__fmul_rn(BETA, m0), xv.x), r0);
        m1 = __fsub_rn(__fadd_rn(__fmul_rn(BETA, m1), xv.y), r1);
        m2 = __fsub_rn(__fadd_rn(__fmul_rn(BETA, m2), xv.z), r2);
        m3 = __fsub_rn(__fadd_rn(__fmul_rn(BETA, m3), xv.w), r3);

        float4 s;
        s.x = (m0 > THR) ? 1.0f : 0.0f;
        s.y = (m1 > THR) ? 1.0f : 0.0f;
        s.z = (m2 > THR) ? 1.0f : 0.0f;
        s.w = (m3 > THR) ? 1.0f : 0.0f;

        __stcs(o + (size_t)t * n4, s);   // streaming store, evict-first
    }
}

// Generic step count (runtime loop) — same math.
__global__ __launch_bounds__(SNN_THREADS)
void snn_kernel_generic4(const float4* __restrict__ x, float4* __restrict__ out,
                         int n4, int nsteps)
{
    int i = blockIdx.x * SNN_THREADS + threadIdx.x;
    if (i >= n4) return;

    const float4 xv = x[i];
    float m0 = 0.0f, m1 = 0.0f, m2 = 0.0f, m3 = 0.0f;
    float4* o = out + i;

    for (int t = 0; t < nsteps; ++t) {
        const float r0 = (m0 > THR) ? THR : 0.0f;
        const float r1 = (m1 > THR) ? THR : 0.0f;
        const float r2 = (m2 > THR) ? THR : 0.0f;
        const float r3 = (m3 > THR) ? THR : 0.0f;
        m0 = __fsub_rn(__fadd_rn(__fmul_rn(BETA, m0), xv.x), r0);
        m1 = __fsub_rn(__fadd_rn(__fmul_rn(BETA, m1), xv.y), r1);
        m2 = __fsub_rn(__fadd_rn(__fmul_rn(BETA, m2), xv.z), r2);
        m3 = __fsub_rn(__fadd_rn(__fmul_rn(BETA, m3), xv.w), r3);

        float4 s;
        s.x = (m0 > THR) ? 1.0f : 0.0f;
        s.y = (m1 > THR) ? 1.0f : 0.0f;
        s.z = (m2 > THR) ? 1.0f : 0.0f;
        s.w = (m3 > THR) ? 1.0f : 0.0f;
        __stcs(o + (size_t)t * n4, s);
    }
}

// Scalar tail for n % 4 != 0 (not hit for this shape).
__global__ __launch_bounds__(SNN_THREADS)
void snn_kernel_tail(const float* __restrict__ x, float* __restrict__ out,
                     int start, int n, int nsteps)
{
    int i = start + blockIdx.x * SNN_THREADS + threadIdx.x;
    if (i >= n) return;

    const float xv = x[i];
    float m = 0.0f;
    for (int t = 0; t < nsteps; ++t) {
        const float r = (m > THR) ? THR : 0.0f;
        m = __fsub_rn(__fadd_rn(__fmul_rn(BETA, m), xv), r);
        out[(size_t)t * n + i] = (m > THR) ? 1.0f : 0.0f;
    }
}

extern "C" void kernel_launch(void* const* d_in, const int* in_sizes, int n_in,
                              void* d_out, int out_size)
{
    const float* x = (const float*)d_in[0];
    float* out = (float*)d_out;

    const int n = in_sizes[0];                 // 3,145,728 elements
    const int nsteps = out_size / n;           // 50

    const int n4 = n / 4;
    const int tail = n - n4 * 4;

    if (n4 > 0) {
        const int grid = (n4 + SNN_THREADS - 1) / SNN_THREADS;
        if (nsteps == 50) {
            snn_kernel_fixed<50><<<grid, SNN_THREADS>>>(
                (const float4*)x, (float4*)out, n4);
        } else {
            snn_kernel_generic4<<<grid, SNN_THREADS>>>(
                (const float4*)x, (float4*)out, n4, nsteps);
        }
    }
    if (tail > 0) {
        snn_kernel_tail<<<1, SNN_THREADS>>>(x, out, n4 * 4, n, nsteps);
    }
}